// round 1
// baseline (speedup 1.0000x reference)
#include <cuda_runtime.h>
#include <cstdint>
#include <cstddef>

#define NVN 50000
#define NCN 20000
#define HD  256
#define NLAYER 4
#define EVVN 500000
#define EVCN 300000
#define GN  64

// ---------------- scratch (device globals; allowed) ----------------
__device__ __align__(128) float g_XV0[NVN * HD];
__device__ __align__(128) float g_XV1[NVN * HD];
__device__ __align__(128) float g_XC0[NCN * HD];
__device__ __align__(128) float g_XC1[NCN * HD];
__device__ __align__(128) float g_XL0[NVN * HD];
__device__ __align__(128) float g_XL1[NVN * HD];
__device__ __align__(128) float g_XL2[NVN * HD];
__device__ __align__(128) float g_XL3[NCN * HD];

__device__ float g_AS0[NVN], g_AD0[NVN];
__device__ float g_AS1[NVN], g_AD1[NVN];
__device__ float g_AS2[NVN], g_AD3[NVN];
__device__ float g_AS3[NCN], g_AD2[NCN];

__device__ unsigned g_M0[NVN], g_M1[NVN], g_M3[NVN], g_M2[NCN];
__device__ float    g_D0[NVN], g_D1[NVN], g_D3[NVN], g_D2[NCN];

__device__ float g_EX0[EVVN], g_EX1[EVVN], g_EX2[EVCN], g_EX3[EVCN];

__device__ float g_WS[16 * HD];  // [l*4+k][H]  = W_src[l,k] @ att_src[l,k]
__device__ float g_WD[16 * HD];  // [l*4+k][H]  = W_dst[l,k] @ att_dst[l,k]

__device__ __align__(128) float g_VP[GN * HD];
__device__ __align__(128) float g_CP[GN * HD];
__device__ int   g_CNT[2 * GN];

// ---------------- helpers ----------------
__device__ __forceinline__ unsigned fflip(float f) {
    unsigned u = __float_as_uint(f);
    return (u & 0x80000000u) ? ~u : (u | 0x80000000u);
}
__device__ __forceinline__ float funflip(unsigned u) {
    return (u & 0x80000000u) ? __uint_as_float(u & 0x7fffffffu)
                             : __uint_as_float(~u);
}
__device__ __forceinline__ void red4(float* p, float4 v) {
    asm volatile("red.global.add.v4.f32 [%0], {%1,%2,%3,%4};"
                 :: "l"(p), "f"(v.x), "f"(v.y), "f"(v.z), "f"(v.w) : "memory");
}

// ---------------- ws/wd precompute: ws[i] = sum_j W[i][j]*a[j] ----------------
__global__ void wsd_kernel(const float* __restrict__ Wsrc, const float* __restrict__ Wdst,
                           const float* __restrict__ as, const float* __restrict__ ad) {
    int b = blockIdx.x;        // 0..15 = l*4+k
    int i = threadIdx.x;       // 0..255
    __shared__ float sas[HD], sad[HD];
    sas[i] = as[b * HD + i];
    sad[i] = ad[b * HD + i];
    __syncthreads();
    const float* Ws = Wsrc + (size_t)b * HD * HD + (size_t)i * HD;
    const float* Wd = Wdst + (size_t)b * HD * HD + (size_t)i * HD;
    float s = 0.f, d = 0.f;
    #pragma unroll 8
    for (int j = 0; j < HD; j++) { s += Ws[j] * sas[j]; d += Wd[j] * sad[j]; }
    g_WS[b * HD + i] = s;
    g_WD[b * HD + i] = d;
}

// ---------------- tiled SGEMM: C[N,256] = A[N,256] @ W[256,256] ----------------
__global__ void sgemm_kernel(const float* __restrict__ A, const float* __restrict__ W,
                             float* __restrict__ C, int N) {
    __shared__ float sA[16][64];
    __shared__ float sB[16][64];
    const int t  = threadIdx.x;          // 256 threads
    const int tx = t & 15, ty = t >> 4;
    const int row0 = blockIdx.x * 64, col0 = blockIdx.y * 64;
    float acc[4][4] = {};
    for (int k0 = 0; k0 < HD; k0 += 16) {
        {   // A tile: 64 rows x 16 k-cols
            int r = t >> 2, c4 = (t & 3) * 4;
            float4 av = make_float4(0.f, 0.f, 0.f, 0.f);
            if (row0 + r < N)
                av = *(const float4*)(A + (size_t)(row0 + r) * HD + k0 + c4);
            sA[c4 + 0][r] = av.x; sA[c4 + 1][r] = av.y;
            sA[c4 + 2][r] = av.z; sA[c4 + 3][r] = av.w;
        }
        #pragma unroll
        for (int i = 0; i < 4; i++) {    // W tile: 16 k-rows x 64 cols
            int r = (t >> 6) + i * 4, c = t & 63;
            sB[r][c] = W[(size_t)(k0 + r) * HD + col0 + c];
        }
        __syncthreads();
        #pragma unroll
        for (int kk = 0; kk < 16; kk++) {
            float4 a = *(const float4*)&sA[kk][ty * 4];
            float4 b = *(const float4*)&sB[kk][tx * 4];
            float av[4] = {a.x, a.y, a.z, a.w};
            float bv[4] = {b.x, b.y, b.z, b.w};
            #pragma unroll
            for (int i = 0; i < 4; i++)
                #pragma unroll
                for (int j = 0; j < 4; j++)
                    acc[i][j] += av[i] * bv[j];
        }
        __syncthreads();
    }
    #pragma unroll
    for (int i = 0; i < 4; i++) {
        int gr = row0 + ty * 4 + i;
        if (gr < N)
            *(float4*)(C + (size_t)gr * HD + col0 + tx * 4) =
                make_float4(acc[i][0], acc[i][1], acc[i][2], acc[i][3]);
    }
}

// ---------------- attention-scalar dots ----------------
__global__ void avec_var_kernel(const float* __restrict__ xv, int l) {
    __shared__ float sv[6][HD];
    int t = threadIdx.x;
    sv[0][t] = g_WS[(4 * l + 0) * HD + t];
    sv[1][t] = g_WD[(4 * l + 0) * HD + t];
    sv[2][t] = g_WS[(4 * l + 1) * HD + t];
    sv[3][t] = g_WD[(4 * l + 1) * HD + t];
    sv[4][t] = g_WS[(4 * l + 2) * HD + t];
    sv[5][t] = g_WD[(4 * l + 3) * HD + t];
    __syncthreads();
    int w = (blockIdx.x * blockDim.x + t) >> 5;
    int lane = t & 31;
    if (w >= NVN) return;
    const float* row = xv + (size_t)w * HD;
    float s[6] = {0, 0, 0, 0, 0, 0};
    #pragma unroll
    for (int j0 = 0; j0 < HD; j0 += 32) {
        float x = row[j0 + lane];
        #pragma unroll
        for (int k = 0; k < 6; k++) s[k] += x * sv[k][j0 + lane];
    }
    #pragma unroll
    for (int k = 0; k < 6; k++)
        #pragma unroll
        for (int o = 16; o > 0; o >>= 1) s[k] += __shfl_xor_sync(0xffffffffu, s[k], o);
    if (lane == 0) {
        g_AS0[w] = s[0]; g_AD0[w] = s[1];
        g_AS1[w] = s[2]; g_AD1[w] = s[3];
        g_AS2[w] = s[4]; g_AD3[w] = s[5];
    }
}

__global__ void avec_con_kernel(const float* __restrict__ xc, int l) {
    __shared__ float sv[2][HD];
    int t = threadIdx.x;
    sv[0][t] = g_WD[(4 * l + 2) * HD + t];  // a_dst for vc GAT (dst=con)
    sv[1][t] = g_WS[(4 * l + 3) * HD + t];  // a_src for cv GAT (src=con)
    __syncthreads();
    int w = (blockIdx.x * blockDim.x + t) >> 5;
    int lane = t & 31;
    if (w >= NCN) return;
    const float* row = xc + (size_t)w * HD;
    float s0 = 0.f, s1 = 0.f;
    #pragma unroll
    for (int j0 = 0; j0 < HD; j0 += 32) {
        float x = row[j0 + lane];
        s0 += x * sv[0][j0 + lane];
        s1 += x * sv[1][j0 + lane];
    }
    #pragma unroll
    for (int o = 16; o > 0; o >>= 1) {
        s0 += __shfl_xor_sync(0xffffffffu, s0, o);
        s1 += __shfl_xor_sync(0xffffffffu, s1, o);
    }
    if (lane == 0) { g_AD2[w] = s0; g_AS3[w] = s1; }
}

// ---------------- per-layer init ----------------
__global__ void init_var_kernel(float* __restrict__ vnew, const float* __restrict__ bias, int l) {
    int n = blockIdx.x;          // grid = NVN
    int h = threadIdx.x;         // 256
    vnew[(size_t)n * HD + h] = bias[(4 * l + 0) * HD + h]
                             + bias[(4 * l + 1) * HD + h]
                             + bias[(4 * l + 3) * HD + h];
    if (h == 0) {
        g_M0[n] = 0u; g_M1[n] = 0u; g_M3[n] = 0u;
        g_D0[n] = 0.f; g_D1[n] = 0.f; g_D3[n] = 0.f;
    }
}
__global__ void init_con_kernel(float* __restrict__ cnew, const float* __restrict__ bias, int l) {
    int n = blockIdx.x;          // grid = NCN
    int h = threadIdx.x;
    cnew[(size_t)n * HD + h] = bias[(4 * l + 2) * HD + h];
    if (h == 0) { g_M2[n] = 0u; g_D2[n] = 0.f; }
}

// ---------------- edge passes ----------------
__global__ void edge_max_kernel(const int* __restrict__ src, const int* __restrict__ dst,
                                const float* __restrict__ AS, const float* __restrict__ AD,
                                float* __restrict__ EX, unsigned* __restrict__ M, int E) {
    int i = blockIdx.x * blockDim.x + threadIdx.x;
    if (i >= E) return;
    int s = src[i], d = dst[i];
    float e = AS[s] + AD[d];
    e = (e >= 0.f) ? e : 0.2f * e;         // leaky_relu slope 0.2
    EX[i] = e;
    atomicMax(&M[d], fflip(e));
}

__global__ void edge_expden_kernel(const int* __restrict__ dst,
                                   float* __restrict__ EX, const unsigned* __restrict__ M,
                                   float* __restrict__ D, int E) {
    int i = blockIdx.x * blockDim.x + threadIdx.x;
    if (i >= E) return;
    int d = dst[i];
    float ex = __expf(EX[i] - funflip(M[d]));
    EX[i] = ex;
    atomicAdd(&D[d], ex);
}

__global__ void edge_agg_kernel(const int* __restrict__ src, const int* __restrict__ dst,
                                const float* __restrict__ EX, const float* __restrict__ D,
                                const float* __restrict__ XL, float* __restrict__ out, int E) {
    int g = (blockIdx.x * blockDim.x + threadIdx.x) >> 5;
    int lane = threadIdx.x & 31;
    if (g >= E) return;
    int s = src[g], d = dst[g];
    float w = EX[g] / (D[d] + 1e-16f);
    const float4* xs = (const float4*)(XL + (size_t)s * HD);
    float* ob = out + (size_t)d * HD;
    #pragma unroll
    for (int j = 0; j < 2; j++) {
        int idx = lane + 32 * j;
        float4 v = xs[idx];
        v.x *= w; v.y *= w; v.z *= w; v.w *= w;
        red4(ob + 4 * idx, v);
    }
}

// ---------------- pooling + head ----------------
__global__ void zero_pool_kernel() {
    int i = blockIdx.x * 256 + threadIdx.x;   // grid = GN blocks -> GN*256 threads
    g_VP[i] = 0.f;
    g_CP[i] = 0.f;
    if (i < 2 * GN) g_CNT[i] = 0;
}

__global__ void pool_kernel(const float* __restrict__ X, const int* __restrict__ batch,
                            int N, float* __restrict__ S, int* __restrict__ cnt) {
    int w = (blockIdx.x * blockDim.x + threadIdx.x) >> 5;
    int lane = threadIdx.x & 31;
    if (w >= N) return;
    int g = batch[w];
    if (lane == 0) atomicAdd(&cnt[g], 1);
    const float4* xr = (const float4*)(X + (size_t)w * HD);
    float* sb = S + (size_t)g * HD;
    #pragma unroll
    for (int j = 0; j < 2; j++) {
        int idx = lane + 32 * j;
        red4(sb + 4 * idx, xr[idx]);
    }
}

__global__ void finalize_kernel(const float* __restrict__ Wlin, const float* __restrict__ blin,
                                float* __restrict__ out) {
    int g = blockIdx.x, t = threadIdx.x;
    float cv = (float)max(g_CNT[g], 1);
    float cc = (float)max(g_CNT[GN + g], 1);
    float a = g_VP[g * HD + t] / cv;
    float c = g_CP[g * HD + t] / cc;
    float p0 = a * Wlin[t * 2 + 0] + c * Wlin[(HD + t) * 2 + 0];
    float p1 = a * Wlin[t * 2 + 1] + c * Wlin[(HD + t) * 2 + 1];
    __shared__ float s0[256], s1[256];
    s0[t] = p0; s1[t] = p1;
    __syncthreads();
    for (int o = 128; o > 0; o >>= 1) {
        if (t < o) { s0[t] += s0[t + o]; s1[t] += s1[t + o]; }
        __syncthreads();
    }
    if (t == 0) {
        float z0 = s0[0] + blin[0], z1 = s1[0] + blin[1];
        float m = fmaxf(z0, z1);
        float e0 = expf(z0 - m), e1 = expf(z1 - m);
        float inv = 1.f / (e0 + e1);
        out[2 * g + 0] = e0 * inv;
        out[2 * g + 1] = e1 * inv;
    }
}

// ---------------- host ----------------
extern "C" void kernel_launch(void* const* d_in, const int* in_sizes, int n_in,
                              void* d_out, int out_size) {
    const float* x_var   = (const float*)d_in[0];
    const float* x_con   = (const float*)d_in[1];
    const float* W_src   = (const float*)d_in[2];
    const float* W_dst   = (const float*)d_in[3];
    const float* att_src = (const float*)d_in[4];
    const float* att_dst = (const float*)d_in[5];
    const float* bias    = (const float*)d_in[6];
    const float* W_lin   = (const float*)d_in[7];
    const float* b_lin   = (const float*)d_in[8];
    const int* e_vv      = (const int*)d_in[9];
    const int* e_vv_rev  = (const int*)d_in[10];
    const int* e_vc      = (const int*)d_in[11];
    const int* e_cv      = (const int*)d_in[12];
    const int* batch_var = (const int*)d_in[13];
    const int* batch_con = (const int*)d_in[14];
    float* out = (float*)d_out;

    float *pXV[2], *pXC[2], *pXL0, *pXL1, *pXL2, *pXL3, *pVP, *pCP;
    float *pEX0, *pEX1, *pEX2, *pEX3, *pD0, *pD1, *pD2, *pD3;
    unsigned *pM0, *pM1, *pM2, *pM3;
    float *pAS0, *pAD0, *pAS1, *pAD1, *pAS2, *pAD3, *pAS3, *pAD2;
    int* pCNT;
    cudaGetSymbolAddress((void**)&pXV[0], g_XV0);
    cudaGetSymbolAddress((void**)&pXV[1], g_XV1);
    cudaGetSymbolAddress((void**)&pXC[0], g_XC0);
    cudaGetSymbolAddress((void**)&pXC[1], g_XC1);
    cudaGetSymbolAddress((void**)&pXL0, g_XL0);
    cudaGetSymbolAddress((void**)&pXL1, g_XL1);
    cudaGetSymbolAddress((void**)&pXL2, g_XL2);
    cudaGetSymbolAddress((void**)&pXL3, g_XL3);
    cudaGetSymbolAddress((void**)&pEX0, g_EX0);
    cudaGetSymbolAddress((void**)&pEX1, g_EX1);
    cudaGetSymbolAddress((void**)&pEX2, g_EX2);
    cudaGetSymbolAddress((void**)&pEX3, g_EX3);
    cudaGetSymbolAddress((void**)&pM0, g_M0);
    cudaGetSymbolAddress((void**)&pM1, g_M1);
    cudaGetSymbolAddress((void**)&pM2, g_M2);
    cudaGetSymbolAddress((void**)&pM3, g_M3);
    cudaGetSymbolAddress((void**)&pD0, g_D0);
    cudaGetSymbolAddress((void**)&pD1, g_D1);
    cudaGetSymbolAddress((void**)&pD2, g_D2);
    cudaGetSymbolAddress((void**)&pD3, g_D3);
    cudaGetSymbolAddress((void**)&pAS0, g_AS0);
    cudaGetSymbolAddress((void**)&pAD0, g_AD0);
    cudaGetSymbolAddress((void**)&pAS1, g_AS1);
    cudaGetSymbolAddress((void**)&pAD1, g_AD1);
    cudaGetSymbolAddress((void**)&pAS2, g_AS2);
    cudaGetSymbolAddress((void**)&pAD3, g_AD3);
    cudaGetSymbolAddress((void**)&pAS3, g_AS3);
    cudaGetSymbolAddress((void**)&pAD2, g_AD2);
    cudaGetSymbolAddress((void**)&pVP, g_VP);
    cudaGetSymbolAddress((void**)&pCP, g_CP);
    cudaGetSymbolAddress((void**)&pCNT, g_CNT);

    // 16 (ws, wd) projection vectors
    wsd_kernel<<<16, 256>>>(W_src, W_dst, att_src, att_dst);

    const int EB = 256;
    dim3 gemmGridV((NVN + 63) / 64, 4);
    dim3 gemmGridC((NCN + 63) / 64, 4);
    int avecBlocksV = (NVN * 32 + EB - 1) / EB;
    int avecBlocksC = (NCN * 32 + EB - 1) / EB;
    int aggBlocksVV = (EVVN * 32 + EB - 1) / EB;
    int aggBlocksVC = (EVCN * 32 + EB - 1) / EB;

    for (int l = 0; l < NLAYER; l++) {
        const float* xv_in = (l == 0) ? x_var : pXV[(l + 1) & 1];
        const float* xc_in = (l == 0) ? x_con : pXC[(l + 1) & 1];
        float* xv_out = pXV[l & 1];
        float* xc_out = pXC[l & 1];
        const float* Wl = W_src + (size_t)(4 * l) * HD * HD;

        sgemm_kernel<<<gemmGridV, 256>>>(xv_in, Wl + 0 * (size_t)HD * HD, pXL0, NVN);
        sgemm_kernel<<<gemmGridV, 256>>>(xv_in, Wl + 1 * (size_t)HD * HD, pXL1, NVN);
        sgemm_kernel<<<gemmGridV, 256>>>(xv_in, Wl + 2 * (size_t)HD * HD, pXL2, NVN);
        sgemm_kernel<<<gemmGridC, 256>>>(xc_in, Wl + 3 * (size_t)HD * HD, pXL3, NCN);

        avec_var_kernel<<<avecBlocksV, EB>>>(xv_in, l);
        avec_con_kernel<<<avecBlocksC, EB>>>(xc_in, l);

        init_var_kernel<<<NVN, 256>>>(xv_out, bias, l);
        init_con_kernel<<<NCN, 256>>>(xc_out, bias, l);

        // GAT0: e_vv (src=var row0, dst=var row1) -> xv_out
        edge_max_kernel<<<(EVVN + EB - 1) / EB, EB>>>(e_vv, e_vv + EVVN, pAS0, pAD0, pEX0, pM0, EVVN);
        edge_expden_kernel<<<(EVVN + EB - 1) / EB, EB>>>(e_vv + EVVN, pEX0, pM0, pD0, EVVN);
        edge_agg_kernel<<<aggBlocksVV, EB>>>(e_vv, e_vv + EVVN, pEX0, pD0, pXL0, xv_out, EVVN);

        // GAT1: e_vv_rev -> xv_out
        edge_max_kernel<<<(EVVN + EB - 1) / EB, EB>>>(e_vv_rev, e_vv_rev + EVVN, pAS1, pAD1, pEX1, pM1, EVVN);
        edge_expden_kernel<<<(EVVN + EB - 1) / EB, EB>>>(e_vv_rev + EVVN, pEX1, pM1, pD1, EVVN);
        edge_agg_kernel<<<aggBlocksVV, EB>>>(e_vv_rev, e_vv_rev + EVVN, pEX1, pD1, pXL1, xv_out, EVVN);

        // GAT3: e_cv (src=con row0, dst=var row1) -> xv_out
        edge_max_kernel<<<(EVCN + EB - 1) / EB, EB>>>(e_cv, e_cv + EVCN, pAS3, pAD3, pEX3, pM3, EVCN);
        edge_expden_kernel<<<(EVCN + EB - 1) / EB, EB>>>(e_cv + EVCN, pEX3, pM3, pD3, EVCN);
        edge_agg_kernel<<<aggBlocksVC, EB>>>(e_cv, e_cv + EVCN, pEX3, pD3, pXL3, xv_out, EVCN);

        // GAT2: e_vc (src=var row0, dst=con row1) -> xc_out
        edge_max_kernel<<<(EVCN + EB - 1) / EB, EB>>>(e_vc, e_vc + EVCN, pAS2, pAD2, pEX2, pM2, EVCN);
        edge_expden_kernel<<<(EVCN + EB - 1) / EB, EB>>>(e_vc + EVCN, pEX2, pM2, pD2, EVCN);
        edge_agg_kernel<<<aggBlocksVC, EB>>>(e_vc, e_vc + EVCN, pEX2, pD2, pXL2, xc_out, EVCN);
    }

    // pooling + linear head + softmax
    zero_pool_kernel<<<GN, 256>>>();
    pool_kernel<<<avecBlocksV, EB>>>(pXV[(NLAYER - 1) & 1], batch_var, NVN, pVP, pCNT);
    pool_kernel<<<avecBlocksC, EB>>>(pXC[(NLAYER - 1) & 1], batch_con, NCN, pCP, pCNT + GN);
    finalize_kernel<<<GN, 256>>>(W_lin, b_lin, out);
}

// round 4
// speedup vs baseline: 1.0484x; 1.0484x over previous
#include <cuda_runtime.h>
#include <cstdint>
#include <cstddef>

#define NVN 50000
#define NCN 20000
#define HD  256
#define NLAYER 4
#define EVVN 500000
#define EVCN 300000
#define GN  64

// ---------------- scratch (device globals; allowed) ----------------
__device__ __align__(128) float g_XV0[NVN * HD];
__device__ __align__(128) float g_XV1[NVN * HD];
__device__ __align__(128) float g_XC0[NCN * HD];
__device__ __align__(128) float g_XC1[NCN * HD];
__device__ __align__(128) float g_XL0[NVN * HD];
__device__ __align__(128) float g_XL1[NVN * HD];
__device__ __align__(128) float g_XL2[NVN * HD];
__device__ __align__(128) float g_XL3[NCN * HD];

__device__ float g_AS0[NVN], g_AD0[NVN];
__device__ float g_AS1[NVN], g_AD1[NVN];
__device__ float g_AS2[NVN], g_AD3[NVN];
__device__ float g_AS3[NCN], g_AD2[NCN];

__device__ unsigned g_M0[NVN], g_M1[NVN], g_M3[NVN], g_M2[NCN];
__device__ float    g_D0[NVN], g_D1[NVN], g_D3[NVN], g_D2[NCN];

__device__ float g_EX0[EVVN], g_EX1[EVVN], g_EX2[EVCN], g_EX3[EVCN];

__device__ float g_WS[16 * HD];
__device__ float g_WD[16 * HD];

__device__ __align__(128) float g_VP[GN * HD];
__device__ __align__(128) float g_CP[GN * HD];
__device__ int   g_CNT[2 * GN];

// ---------------- helpers ----------------
__device__ __forceinline__ unsigned fflip(float f) {
    unsigned u = __float_as_uint(f);
    return (u & 0x80000000u) ? ~u : (u | 0x80000000u);
}
__device__ __forceinline__ float funflip(unsigned u) {
    return (u & 0x80000000u) ? __uint_as_float(u & 0x7fffffffu)
                             : __uint_as_float(~u);
}
__device__ __forceinline__ void red4(float* p, float4 v) {
    asm volatile("red.global.add.v4.f32 [%0], {%1,%2,%3,%4};"
                 :: "l"(p), "f"(v.x), "f"(v.y), "f"(v.z), "f"(v.w) : "memory");
}
// tf32 cvt: destination must be a .b32 register at PTX level
__device__ __forceinline__ void tf32split(float x, float& hi, float& lo) {
    uint32_t hb, lb;
    asm("cvt.rna.tf32.f32 %0, %1;" : "=r"(hb) : "f"(x));
    float hf = __uint_as_float(hb);
    float r = x - hf;
    asm("cvt.rna.tf32.f32 %0, %1;" : "=r"(lb) : "f"(r));
    hi = hf;
    lo = __uint_as_float(lb);
}
__device__ __forceinline__ void ldsm4(uint32_t* r, const float* p) {
    uint32_t addr = (uint32_t)__cvta_generic_to_shared(p);
    asm volatile("ldmatrix.sync.aligned.m8n8.x4.shared.b16 {%0,%1,%2,%3}, [%4];"
                 : "=r"(r[0]), "=r"(r[1]), "=r"(r[2]), "=r"(r[3]) : "r"(addr));
}
__device__ __forceinline__ void mma_tf32(float* c, const uint32_t* a, const uint32_t* b) {
    asm volatile(
        "mma.sync.aligned.m16n8k8.row.col.f32.tf32.tf32.f32 "
        "{%0,%1,%2,%3}, {%4,%5,%6,%7}, {%8,%9}, {%0,%1,%2,%3};"
        : "+f"(c[0]), "+f"(c[1]), "+f"(c[2]), "+f"(c[3])
        : "r"(a[0]), "r"(a[1]), "r"(a[2]), "r"(a[3]), "r"(b[0]), "r"(b[1]));
}

// ---------------- ws/wd precompute ----------------
__global__ void wsd_kernel(const float* __restrict__ Wsrc, const float* __restrict__ Wdst,
                           const float* __restrict__ as, const float* __restrict__ ad) {
    int b = blockIdx.x;
    int i = threadIdx.x;
    __shared__ float sas[HD], sad[HD];
    sas[i] = as[b * HD + i];
    sad[i] = ad[b * HD + i];
    __syncthreads();
    const float* Ws = Wsrc + (size_t)b * HD * HD + (size_t)i * HD;
    const float* Wd = Wdst + (size_t)b * HD * HD + (size_t)i * HD;
    float s = 0.f, d = 0.f;
    #pragma unroll 8
    for (int j = 0; j < HD; j++) { s += Ws[j] * sas[j]; d += Wd[j] * sad[j]; }
    g_WS[b * HD + i] = s;
    g_WD[b * HD + i] = d;
}

// ---------------- tf32x3 tensor-core GEMM: C[N,256] = A[N,256] @ W[256,256] ----------
// block tile 128x64, BK=16, 8 warps (4m x 2n), warp tile 32x32 (2x4 m16n8k8 tiles)
__global__ __launch_bounds__(256) void gemm_tf32_kernel(
        const float* __restrict__ A, const float* __restrict__ W,
        float* __restrict__ C, int N) {
    __shared__ __align__(16) float sAh[128][20];
    __shared__ __align__(16) float sAl[128][20];
    __shared__ __align__(16) float sBh[64][20];   // transposed: [n][k]
    __shared__ __align__(16) float sBl[64][20];

    const int tid = threadIdx.x;
    const int lane = tid & 31;
    const int wid = tid >> 5;
    const int wm = (wid & 3) * 32;
    const int wn = (wid >> 2) * 32;
    const int row0 = blockIdx.x * 128;
    const int col0 = blockIdx.y * 64;

    const int ar = tid >> 2;            // 0..63 (rows ar and ar+64)
    const int ac = (tid & 3) * 4;       // k-offset 0,4,8,12
    const int bkr = tid >> 4;           // 0..15 (k row of W slice)
    const int bnc = (tid & 15) * 4;     // 0..60 (n col)

    float4 a0p = make_float4(0, 0, 0, 0), a1p = make_float4(0, 0, 0, 0), bp;
    if (row0 + ar < N)      a0p = *(const float4*)(A + (size_t)(row0 + ar) * HD + ac);
    if (row0 + ar + 64 < N) a1p = *(const float4*)(A + (size_t)(row0 + ar + 64) * HD + ac);
    bp = *(const float4*)(W + (size_t)bkr * HD + col0 + bnc);

    float acc[2][4][4];
    #pragma unroll
    for (int i = 0; i < 2; i++)
        #pragma unroll
        for (int j = 0; j < 4; j++)
            #pragma unroll
            for (int q = 0; q < 4; q++) acc[i][j][q] = 0.f;

    const int g = lane >> 2, t4 = lane & 3;
    const int lrow = (lane & 7) + ((lane >> 3) & 1) * 8;
    const int lcol = (lane >> 4) << 2;

    for (int k0 = 0; k0 < HD; k0 += 16) {
        {
            float h, lo;
            float av[4] = {a0p.x, a0p.y, a0p.z, a0p.w};
            #pragma unroll
            for (int q = 0; q < 4; q++) {
                tf32split(av[q], h, lo);
                sAh[ar][ac + q] = h; sAl[ar][ac + q] = lo;
            }
            float av2[4] = {a1p.x, a1p.y, a1p.z, a1p.w};
            #pragma unroll
            for (int q = 0; q < 4; q++) {
                tf32split(av2[q], h, lo);
                sAh[ar + 64][ac + q] = h; sAl[ar + 64][ac + q] = lo;
            }
            float bv[4] = {bp.x, bp.y, bp.z, bp.w};
            #pragma unroll
            for (int q = 0; q < 4; q++) {
                tf32split(bv[q], h, lo);
                sBh[bnc + q][bkr] = h; sBl[bnc + q][bkr] = lo;
            }
        }
        __syncthreads();

        if (k0 + 16 < HD) {
            int kn = k0 + 16;
            a0p = make_float4(0, 0, 0, 0); a1p = make_float4(0, 0, 0, 0);
            if (row0 + ar < N)      a0p = *(const float4*)(A + (size_t)(row0 + ar) * HD + kn + ac);
            if (row0 + ar + 64 < N) a1p = *(const float4*)(A + (size_t)(row0 + ar + 64) * HD + kn + ac);
            bp = *(const float4*)(W + (size_t)(kn + bkr) * HD + col0 + bnc);
        }

        #pragma unroll
        for (int kk = 0; kk < 2; kk++) {
            const int kb = kk * 8;
            uint32_t ah[2][4], al[2][4];
            #pragma unroll
            for (int i = 0; i < 2; i++) {
                int base = wm + i * 16;
                ldsm4(ah[i], &sAh[base + lrow][kb + lcol]);
                ldsm4(al[i], &sAl[base + lrow][kb + lcol]);
            }
            uint32_t bh[4][2], bl[4][2];
            #pragma unroll
            for (int j = 0; j < 4; j++) {
                int n = wn + j * 8 + g;
                bh[j][0] = __float_as_uint(sBh[n][kb + t4]);
                bh[j][1] = __float_as_uint(sBh[n][kb + t4 + 4]);
                bl[j][0] = __float_as_uint(sBl[n][kb + t4]);
                bl[j][1] = __float_as_uint(sBl[n][kb + t4 + 4]);
            }
            #pragma unroll
            for (int i = 0; i < 2; i++)
                #pragma unroll
                for (int j = 0; j < 4; j++) {
                    mma_tf32(acc[i][j], ah[i], bh[j]);
                    mma_tf32(acc[i][j], ah[i], bl[j]);
                    mma_tf32(acc[i][j], al[i], bh[j]);
                }
        }
        __syncthreads();
    }

    #pragma unroll
    for (int i = 0; i < 2; i++) {
        int r0 = row0 + wm + i * 16 + g;
        #pragma unroll
        for (int j = 0; j < 4; j++) {
            int c = col0 + wn + j * 8 + t4 * 2;
            if (r0 < N)
                *(float2*)(C + (size_t)r0 * HD + c) = make_float2(acc[i][j][0], acc[i][j][1]);
            if (r0 + 8 < N)
                *(float2*)(C + (size_t)(r0 + 8) * HD + c) = make_float2(acc[i][j][2], acc[i][j][3]);
        }
    }
}

// ---------------- attention-scalar dots ----------------
__global__ void avec_var_kernel(const float* __restrict__ xv, int l) {
    __shared__ float sv[6][HD];
    int t = threadIdx.x;
    sv[0][t] = g_WS[(4 * l + 0) * HD + t];
    sv[1][t] = g_WD[(4 * l + 0) * HD + t];
    sv[2][t] = g_WS[(4 * l + 1) * HD + t];
    sv[3][t] = g_WD[(4 * l + 1) * HD + t];
    sv[4][t] = g_WS[(4 * l + 2) * HD + t];
    sv[5][t] = g_WD[(4 * l + 3) * HD + t];
    __syncthreads();
    int w = (blockIdx.x * blockDim.x + t) >> 5;
    int lane = t & 31;
    if (w >= NVN) return;
    const float* row = xv + (size_t)w * HD;
    float s[6] = {0, 0, 0, 0, 0, 0};
    #pragma unroll
    for (int j0 = 0; j0 < HD; j0 += 32) {
        float x = row[j0 + lane];
        #pragma unroll
        for (int k = 0; k < 6; k++) s[k] += x * sv[k][j0 + lane];
    }
    #pragma unroll
    for (int k = 0; k < 6; k++)
        #pragma unroll
        for (int o = 16; o > 0; o >>= 1) s[k] += __shfl_xor_sync(0xffffffffu, s[k], o);
    if (lane == 0) {
        g_AS0[w] = s[0]; g_AD0[w] = s[1];
        g_AS1[w] = s[2]; g_AD1[w] = s[3];
        g_AS2[w] = s[4]; g_AD3[w] = s[5];
    }
}

__global__ void avec_con_kernel(const float* __restrict__ xc, int l) {
    __shared__ float sv[2][HD];
    int t = threadIdx.x;
    sv[0][t] = g_WD[(4 * l + 2) * HD + t];
    sv[1][t] = g_WS[(4 * l + 3) * HD + t];
    __syncthreads();
    int w = (blockIdx.x * blockDim.x + t) >> 5;
    int lane = t & 31;
    if (w >= NCN) return;
    const float* row = xc + (size_t)w * HD;
    float s0 = 0.f, s1 = 0.f;
    #pragma unroll
    for (int j0 = 0; j0 < HD; j0 += 32) {
        float x = row[j0 + lane];
        s0 += x * sv[0][j0 + lane];
        s1 += x * sv[1][j0 + lane];
    }
    #pragma unroll
    for (int o = 16; o > 0; o >>= 1) {
        s0 += __shfl_xor_sync(0xffffffffu, s0, o);
        s1 += __shfl_xor_sync(0xffffffffu, s1, o);
    }
    if (lane == 0) { g_AD2[w] = s0; g_AS3[w] = s1; }
}

// ---------------- per-layer init ----------------
__global__ void init_var_kernel(float* __restrict__ vnew, const float* __restrict__ bias, int l) {
    int n = blockIdx.x;
    int h = threadIdx.x;
    vnew[(size_t)n * HD + h] = bias[(4 * l + 0) * HD + h]
                             + bias[(4 * l + 1) * HD + h]
                             + bias[(4 * l + 3) * HD + h];
    if (h == 0) {
        g_M0[n] = 0u; g_M1[n] = 0u; g_M3[n] = 0u;
        g_D0[n] = 0.f; g_D1[n] = 0.f; g_D3[n] = 0.f;
    }
}
__global__ void init_con_kernel(float* __restrict__ cnew, const float* __restrict__ bias, int l) {
    int n = blockIdx.x;
    int h = threadIdx.x;
    cnew[(size_t)n * HD + h] = bias[(4 * l + 2) * HD + h];
    if (h == 0) { g_M2[n] = 0u; g_D2[n] = 0.f; }
}

// ---------------- edge passes ----------------
__global__ void edge_max_kernel(const int* __restrict__ src, const int* __restrict__ dst,
                                const float* __restrict__ AS, const float* __restrict__ AD,
                                float* __restrict__ EX, unsigned* __restrict__ M, int E) {
    int i = blockIdx.x * blockDim.x + threadIdx.x;
    if (i >= E) return;
    int s = src[i], d = dst[i];
    float e = AS[s] + AD[d];
    e = (e >= 0.f) ? e : 0.2f * e;
    EX[i] = e;
    atomicMax(&M[d], fflip(e));
}

__global__ void edge_expden_kernel(const int* __restrict__ dst,
                                   float* __restrict__ EX, const unsigned* __restrict__ M,
                                   float* __restrict__ D, int E) {
    int i = blockIdx.x * blockDim.x + threadIdx.x;
    if (i >= E) return;
    int d = dst[i];
    float ex = __expf(EX[i] - funflip(M[d]));
    EX[i] = ex;
    atomicAdd(&D[d], ex);
}

__global__ void edge_agg_kernel(const int* __restrict__ src, const int* __restrict__ dst,
                                const float* __restrict__ EX, const float* __restrict__ D,
                                const float* __restrict__ XL, float* __restrict__ out, int E) {
    int g = (blockIdx.x * blockDim.x + threadIdx.x) >> 5;
    int lane = threadIdx.x & 31;
    if (g >= E) return;
    int s = src[g], d = dst[g];
    float w = EX[g] / (D[d] + 1e-16f);
    const float4* xs = (const float4*)(XL + (size_t)s * HD);
    float* ob = out + (size_t)d * HD;
    #pragma unroll
    for (int j = 0; j < 2; j++) {
        int idx = lane + 32 * j;
        float4 v = xs[idx];
        v.x *= w; v.y *= w; v.z *= w; v.w *= w;
        red4(ob + 4 * idx, v);
    }
}

// ---------------- pooling + head ----------------
__global__ void zero_pool_kernel() {
    int i = blockIdx.x * 256 + threadIdx.x;
    g_VP[i] = 0.f;
    g_CP[i] = 0.f;
    if (i < 2 * GN) g_CNT[i] = 0;
}

__global__ void pool_kernel(const float* __restrict__ X, const int* __restrict__ batch,
                            int N, float* __restrict__ S, int* __restrict__ cnt) {
    int w = (blockIdx.x * blockDim.x + threadIdx.x) >> 5;
    int lane = threadIdx.x & 31;
    if (w >= N) return;
    int g = batch[w];
    if (lane == 0) atomicAdd(&cnt[g], 1);
    const float4* xr = (const float4*)(X + (size_t)w * HD);
    float* sb = S + (size_t)g * HD;
    #pragma unroll
    for (int j = 0; j < 2; j++) {
        int idx = lane + 32 * j;
        red4(sb + 4 * idx, xr[idx]);
    }
}

__global__ void finalize_kernel(const float* __restrict__ Wlin, const float* __restrict__ blin,
                                float* __restrict__ out) {
    int g = blockIdx.x, t = threadIdx.x;
    float cv = (float)max(g_CNT[g], 1);
    float cc = (float)max(g_CNT[GN + g], 1);
    float a = g_VP[g * HD + t] / cv;
    float c = g_CP[g * HD + t] / cc;
    float p0 = a * Wlin[t * 2 + 0] + c * Wlin[(HD + t) * 2 + 0];
    float p1 = a * Wlin[t * 2 + 1] + c * Wlin[(HD + t) * 2 + 1];
    __shared__ float s0[256], s1[256];
    s0[t] = p0; s1[t] = p1;
    __syncthreads();
    for (int o = 128; o > 0; o >>= 1) {
        if (t < o) { s0[t] += s0[t + o]; s1[t] += s1[t + o]; }
        __syncthreads();
    }
    if (t == 0) {
        float z0 = s0[0] + blin[0], z1 = s1[0] + blin[1];
        float m = fmaxf(z0, z1);
        float e0 = expf(z0 - m), e1 = expf(z1 - m);
        float inv = 1.f / (e0 + e1);
        out[2 * g + 0] = e0 * inv;
        out[2 * g + 1] = e1 * inv;
    }
}

// ---------------- host ----------------
extern "C" void kernel_launch(void* const* d_in, const int* in_sizes, int n_in,
                              void* d_out, int out_size) {
    const float* x_var   = (const float*)d_in[0];
    const float* x_con   = (const float*)d_in[1];
    const float* W_src   = (const float*)d_in[2];
    const float* W_dst   = (const float*)d_in[3];
    const float* att_src = (const float*)d_in[4];
    const float* att_dst = (const float*)d_in[5];
    const float* bias    = (const float*)d_in[6];
    const float* W_lin   = (const float*)d_in[7];
    const float* b_lin   = (const float*)d_in[8];
    const int* e_vv      = (const int*)d_in[9];
    const int* e_vv_rev  = (const int*)d_in[10];
    const int* e_vc      = (const int*)d_in[11];
    const int* e_cv      = (const int*)d_in[12];
    const int* batch_var = (const int*)d_in[13];
    const int* batch_con = (const int*)d_in[14];
    float* out = (float*)d_out;

    float *pXV[2], *pXC[2], *pXL0, *pXL1, *pXL2, *pXL3, *pVP, *pCP;
    float *pEX0, *pEX1, *pEX2, *pEX3, *pD0, *pD1, *pD2, *pD3;
    unsigned *pM0, *pM1, *pM2, *pM3;
    float *pAS0, *pAD0, *pAS1, *pAD1, *pAS2, *pAD3, *pAS3, *pAD2;
    int* pCNT;
    cudaGetSymbolAddress((void**)&pXV[0], g_XV0);
    cudaGetSymbolAddress((void**)&pXV[1], g_XV1);
    cudaGetSymbolAddress((void**)&pXC[0], g_XC0);
    cudaGetSymbolAddress((void**)&pXC[1], g_XC1);
    cudaGetSymbolAddress((void**)&pXL0, g_XL0);
    cudaGetSymbolAddress((void**)&pXL1, g_XL1);
    cudaGetSymbolAddress((void**)&pXL2, g_XL2);
    cudaGetSymbolAddress((void**)&pXL3, g_XL3);
    cudaGetSymbolAddress((void**)&pEX0, g_EX0);
    cudaGetSymbolAddress((void**)&pEX1, g_EX1);
    cudaGetSymbolAddress((void**)&pEX2, g_EX2);
    cudaGetSymbolAddress((void**)&pEX3, g_EX3);
    cudaGetSymbolAddress((void**)&pM0, g_M0);
    cudaGetSymbolAddress((void**)&pM1, g_M1);
    cudaGetSymbolAddress((void**)&pM2, g_M2);
    cudaGetSymbolAddress((void**)&pM3, g_M3);
    cudaGetSymbolAddress((void**)&pD0, g_D0);
    cudaGetSymbolAddress((void**)&pD1, g_D1);
    cudaGetSymbolAddress((void**)&pD2, g_D2);
    cudaGetSymbolAddress((void**)&pD3, g_D3);
    cudaGetSymbolAddress((void**)&pAS0, g_AS0);
    cudaGetSymbolAddress((void**)&pAD0, g_AD0);
    cudaGetSymbolAddress((void**)&pAS1, g_AS1);
    cudaGetSymbolAddress((void**)&pAD1, g_AD1);
    cudaGetSymbolAddress((void**)&pAS2, g_AS2);
    cudaGetSymbolAddress((void**)&pAD3, g_AD3);
    cudaGetSymbolAddress((void**)&pAS3, g_AS3);
    cudaGetSymbolAddress((void**)&pAD2, g_AD2);
    cudaGetSymbolAddress((void**)&pVP, g_VP);
    cudaGetSymbolAddress((void**)&pCP, g_CP);
    cudaGetSymbolAddress((void**)&pCNT, g_CNT);

    wsd_kernel<<<16, 256>>>(W_src, W_dst, att_src, att_dst);

    const int EB = 256;
    dim3 gemmGridV((NVN + 127) / 128, 4);
    dim3 gemmGridC((NCN + 127) / 128, 4);
    int avecBlocksV = (NVN * 32 + EB - 1) / EB;
    int avecBlocksC = (NCN * 32 + EB - 1) / EB;
    int aggBlocksVV = (EVVN * 32 + EB - 1) / EB;
    int aggBlocksVC = (EVCN * 32 + EB - 1) / EB;

    for (int l = 0; l < NLAYER; l++) {
        const float* xv_in = (l == 0) ? x_var : pXV[(l + 1) & 1];
        const float* xc_in = (l == 0) ? x_con : pXC[(l + 1) & 1];
        float* xv_out = pXV[l & 1];
        float* xc_out = pXC[l & 1];
        const float* Wl = W_src + (size_t)(4 * l) * HD * HD;

        gemm_tf32_kernel<<<gemmGridV, 256>>>(xv_in, Wl + 0 * (size_t)HD * HD, pXL0, NVN);
        gemm_tf32_kernel<<<gemmGridV, 256>>>(xv_in, Wl + 1 * (size_t)HD * HD, pXL1, NVN);
        gemm_tf32_kernel<<<gemmGridV, 256>>>(xv_in, Wl + 2 * (size_t)HD * HD, pXL2, NVN);
        gemm_tf32_kernel<<<gemmGridC, 256>>>(xc_in, Wl + 3 * (size_t)HD * HD, pXL3, NCN);

        avec_var_kernel<<<avecBlocksV, EB>>>(xv_in, l);
        avec_con_kernel<<<avecBlocksC, EB>>>(xc_in, l);

        init_var_kernel<<<NVN, 256>>>(xv_out, bias, l);
        init_con_kernel<<<NCN, 256>>>(xc_out, bias, l);

        edge_max_kernel<<<(EVVN + EB - 1) / EB, EB>>>(e_vv, e_vv + EVVN, pAS0, pAD0, pEX0, pM0, EVVN);
        edge_expden_kernel<<<(EVVN + EB - 1) / EB, EB>>>(e_vv + EVVN, pEX0, pM0, pD0, EVVN);
        edge_agg_kernel<<<aggBlocksVV, EB>>>(e_vv, e_vv + EVVN, pEX0, pD0, pXL0, xv_out, EVVN);

        edge_max_kernel<<<(EVVN + EB - 1) / EB, EB>>>(e_vv_rev, e_vv_rev + EVVN, pAS1, pAD1, pEX1, pM1, EVVN);
        edge_expden_kernel<<<(EVVN + EB - 1) / EB, EB>>>(e_vv_rev + EVVN, pEX1, pM1, pD1, EVVN);
        edge_agg_kernel<<<aggBlocksVV, EB>>>(e_vv_rev, e_vv_rev + EVVN, pEX1, pD1, pXL1, xv_out, EVVN);

        edge_max_kernel<<<(EVCN + EB - 1) / EB, EB>>>(e_cv, e_cv + EVCN, pAS3, pAD3, pEX3, pM3, EVCN);
        edge_expden_kernel<<<(EVCN + EB - 1) / EB, EB>>>(e_cv + EVCN, pEX3, pM3, pD3, EVCN);
        edge_agg_kernel<<<aggBlocksVC, EB>>>(e_cv, e_cv + EVCN, pEX3, pD3, pXL3, xv_out, EVCN);

        edge_max_kernel<<<(EVCN + EB - 1) / EB, EB>>>(e_vc, e_vc + EVCN, pAS2, pAD2, pEX2, pM2, EVCN);
        edge_expden_kernel<<<(EVCN + EB - 1) / EB, EB>>>(e_vc + EVCN, pEX2, pM2, pD2, EVCN);
        edge_agg_kernel<<<aggBlocksVC, EB>>>(e_vc, e_vc + EVCN, pEX2, pD2, pXL2, xc_out, EVCN);
    }

    zero_pool_kernel<<<GN, 256>>>();
    pool_kernel<<<avecBlocksV, EB>>>(pXV[(NLAYER - 1) & 1], batch_var, NVN, pVP, pCNT);
    pool_kernel<<<avecBlocksC, EB>>>(pXC[(NLAYER - 1) & 1], batch_con, NCN, pCP, pCNT + GN);
    finalize_kernel<<<GN, 256>>>(W_lin, b_lin, out);
}

// round 5
// speedup vs baseline: 1.3162x; 1.2554x over previous
#include <cuda_runtime.h>
#include <cstdint>
#include <cstddef>

#define NVN 50000
#define NCN 20000
#define HD  256
#define NLAYER 4
#define EVVN 500000
#define EVCN 300000
#define GN  64

#define ASTRIDE 20
#define BSTRIDE 72
// dynamic smem floats: A: 2 stages * 128*ASTRIDE * 2(h,l); B: 2 * 16*BSTRIDE * 2
#define SMEM_FLOATS (2*128*ASTRIDE*2 + 2*16*BSTRIDE*2)
#define SMEM_BYTES  (SMEM_FLOATS*4)

// ---------------- scratch (device globals; allowed) ----------------
__device__ __align__(128) float g_XV0[NVN * HD];
__device__ __align__(128) float g_XV1[NVN * HD];
__device__ __align__(128) float g_XC0[NCN * HD];
__device__ __align__(128) float g_XC1[NCN * HD];
__device__ __align__(128) float g_XL0[NVN * HD];
__device__ __align__(128) float g_XL1[NVN * HD];
__device__ __align__(128) float g_XL2[NVN * HD];
__device__ __align__(128) float g_XL3[NCN * HD];

// pre-split tf32 hi/lo buffers
__device__ __align__(128) float g_AhV[NVN * HD];
__device__ __align__(128) float g_AlV[NVN * HD];
__device__ __align__(128) float g_AhC[NCN * HD];
__device__ __align__(128) float g_AlC[NCN * HD];
__device__ __align__(128) float g_Wh[16 * HD * HD];
__device__ __align__(128) float g_Wl[16 * HD * HD];

__device__ float g_AS0[NVN], g_AD0[NVN];
__device__ float g_AS1[NVN], g_AD1[NVN];
__device__ float g_AS2[NVN], g_AD3[NVN];
__device__ float g_AS3[NCN], g_AD2[NCN];

__device__ float g_WS[16 * HD];
__device__ float g_WD[16 * HD];

// CSR structures
__device__ int g_RP0[NVN + 1], g_RP1[NVN + 1], g_RP3[NVN + 1], g_RP2[NCN + 1];
__device__ int g_CU0[NVN], g_CU1[NVN], g_CU3[NVN], g_CU2[NCN];
__device__ int g_CS0[EVVN], g_CS1[EVVN], g_CS3[EVCN], g_CS2[EVCN];

__device__ __align__(128) float g_VP[GN * HD];
__device__ __align__(128) float g_CP[GN * HD];
__device__ int   g_CNT[2 * GN];

// ---------------- helpers ----------------
__device__ __forceinline__ void red4(float* p, float4 v) {
    asm volatile("red.global.add.v4.f32 [%0], {%1,%2,%3,%4};"
                 :: "l"(p), "f"(v.x), "f"(v.y), "f"(v.z), "f"(v.w) : "memory");
}
__device__ __forceinline__ void tf32split(float x, float& hi, float& lo) {
    uint32_t hb, lb;
    asm("cvt.rna.tf32.f32 %0, %1;" : "=r"(hb) : "f"(x));
    float hf = __uint_as_float(hb);
    float r = x - hf;
    asm("cvt.rna.tf32.f32 %0, %1;" : "=r"(lb) : "f"(r));
    hi = hf;
    lo = __uint_as_float(lb);
}
__device__ __forceinline__ void ldsm4(uint32_t* r, const float* p) {
    uint32_t addr = (uint32_t)__cvta_generic_to_shared(p);
    asm volatile("ldmatrix.sync.aligned.m8n8.x4.shared.b16 {%0,%1,%2,%3}, [%4];"
                 : "=r"(r[0]), "=r"(r[1]), "=r"(r[2]), "=r"(r[3]) : "r"(addr));
}
__device__ __forceinline__ void mma_tf32(float* c, const uint32_t* a, const uint32_t* b) {
    asm volatile(
        "mma.sync.aligned.m16n8k8.row.col.f32.tf32.tf32.f32 "
        "{%0,%1,%2,%3}, {%4,%5,%6,%7}, {%8,%9}, {%0,%1,%2,%3};"
        : "+f"(c[0]), "+f"(c[1]), "+f"(c[2]), "+f"(c[3])
        : "r"(a[0]), "r"(a[1]), "r"(a[2]), "r"(a[3]), "r"(b[0]), "r"(b[1]));
}
__device__ __forceinline__ void cpa16(float* dst, const float* src, bool valid) {
    uint32_t d = (uint32_t)__cvta_generic_to_shared(dst);
    int sz = valid ? 16 : 0;
    asm volatile("cp.async.ca.shared.global [%0], [%1], 16, %2;"
                 :: "r"(d), "l"(src), "r"(sz));
}

// ---------------- ws/wd precompute ----------------
__global__ void wsd_kernel(const float* __restrict__ Wsrc, const float* __restrict__ Wdst,
                           const float* __restrict__ as, const float* __restrict__ ad) {
    int b = blockIdx.x;
    int i = threadIdx.x;
    __shared__ float sas[HD], sad[HD];
    sas[i] = as[b * HD + i];
    sad[i] = ad[b * HD + i];
    __syncthreads();
    const float* Ws = Wsrc + (size_t)b * HD * HD + (size_t)i * HD;
    const float* Wd = Wdst + (size_t)b * HD * HD + (size_t)i * HD;
    float s = 0.f, d = 0.f;
    #pragma unroll 8
    for (int j = 0; j < HD; j++) { s += Ws[j] * sas[j]; d += Wd[j] * sad[j]; }
    g_WS[b * HD + i] = s;
    g_WD[b * HD + i] = d;
}

// ---------------- tf32 split (elementwise, vectorized) ----------------
__global__ void split_kernel(const float* __restrict__ X, float* __restrict__ Xh,
                             float* __restrict__ Xl, int n4) {
    int i = blockIdx.x * blockDim.x + threadIdx.x;
    if (i >= n4) return;
    float4 v = ((const float4*)X)[i];
    float4 h, l;
    tf32split(v.x, h.x, l.x);
    tf32split(v.y, h.y, l.y);
    tf32split(v.z, h.z, l.z);
    tf32split(v.w, h.w, l.w);
    ((float4*)Xh)[i] = h;
    ((float4*)Xl)[i] = l;
}

// ---------------- tf32x3 GEMM (pre-split inputs, cp.async double buffer) ----------
// C[N,256] = A[N,256] @ W[256,256], fused over nmat weight matrices (grid.y = 4*nmat)
__global__ __launch_bounds__(256) void gemm_split_kernel(
        const float* __restrict__ Ah, const float* __restrict__ Al,
        const float* __restrict__ Whb, const float* __restrict__ Wlb,
        float* __restrict__ C0, float* __restrict__ C1, float* __restrict__ C2,
        int N) {
    extern __shared__ float sm[];
    float* pAh = sm;
    float* pAl = pAh + 2 * 128 * ASTRIDE;
    float* pBh = pAl + 2 * 128 * ASTRIDE;
    float* pBl = pBh + 2 * 16 * BSTRIDE;

    const int tid = threadIdx.x;
    const int lane = tid & 31;
    const int wid = tid >> 5;
    const int wm = (wid & 3) * 32;
    const int wn = (wid >> 2) * 32;
    const int row0 = blockIdx.x * 128;
    const int mat = blockIdx.y >> 2;
    const int col0 = (blockIdx.y & 3) * 64;
    const float* W_h = Whb + (size_t)mat * HD * HD;
    const float* W_l = Wlb + (size_t)mat * HD * HD;
    float* C = (mat == 0) ? C0 : (mat == 1) ? C1 : C2;

    // staging indices
    const int arow = tid >> 1;                 // 0..127 (A row), 2 float4 per row
    const int acol = (tid & 1) * 8;            // k float offset 0 or 8
    const int brow = tid >> 4;                 // 0..15 (k)
    const int bcol = (tid & 15) * 4;           // 0..60 (n)

    float acc[2][4][4];
    #pragma unroll
    for (int i = 0; i < 2; i++)
        #pragma unroll
        for (int j = 0; j < 4; j++)
            #pragma unroll
            for (int q = 0; q < 4; q++) acc[i][j][q] = 0.f;

    const int g = lane >> 2, t4 = lane & 3;
    const int lrow = (lane & 7) + ((lane >> 3) & 1) * 8;
    const int lcol = (lane >> 4) << 2;

    // stage loader
    auto load_stage = [&](int s, int k0) {
        bool v = (row0 + arow) < N;
        const float* asrc_h = v ? (Ah + (size_t)(row0 + arow) * HD + k0 + acol) : Ah;
        const float* asrc_l = v ? (Al + (size_t)(row0 + arow) * HD + k0 + acol) : Al;
        float* adst_h = pAh + s * 128 * ASTRIDE + arow * ASTRIDE + acol;
        float* adst_l = pAl + s * 128 * ASTRIDE + arow * ASTRIDE + acol;
        cpa16(adst_h,     asrc_h,     v);
        cpa16(adst_h + 4, asrc_h + 4, v);
        cpa16(adst_l,     asrc_l,     v);
        cpa16(adst_l + 4, asrc_l + 4, v);
        const float* bsrc_h = W_h + (size_t)(k0 + brow) * HD + col0 + bcol;
        const float* bsrc_l = W_l + (size_t)(k0 + brow) * HD + col0 + bcol;
        cpa16(pBh + s * 16 * BSTRIDE + brow * BSTRIDE + bcol, bsrc_h, true);
        cpa16(pBl + s * 16 * BSTRIDE + brow * BSTRIDE + bcol, bsrc_l, true);
        asm volatile("cp.async.commit_group;");
    };

    load_stage(0, 0);

    for (int kt = 0; kt < 16; kt++) {
        const int cur = kt & 1;
        if (kt + 1 < 16) {
            load_stage(cur ^ 1, (kt + 1) * 16);
            asm volatile("cp.async.wait_group 1;");
        } else {
            asm volatile("cp.async.wait_group 0;");
        }
        __syncthreads();

        const float* cAh = pAh + cur * 128 * ASTRIDE;
        const float* cAl = pAl + cur * 128 * ASTRIDE;
        const float* cBh = pBh + cur * 16 * BSTRIDE;
        const float* cBl = pBl + cur * 16 * BSTRIDE;

        #pragma unroll
        for (int kk = 0; kk < 2; kk++) {
            const int kb = kk * 8;
            uint32_t ah[2][4], al[2][4];
            #pragma unroll
            for (int i = 0; i < 2; i++) {
                int base = wm + i * 16;
                ldsm4(ah[i], cAh + (base + lrow) * ASTRIDE + kb + lcol);
                ldsm4(al[i], cAl + (base + lrow) * ASTRIDE + kb + lcol);
            }
            uint32_t bh[4][2], bl[4][2];
            #pragma unroll
            for (int j = 0; j < 4; j++) {
                int n = wn + j * 8 + g;
                bh[j][0] = __float_as_uint(cBh[(kb + t4) * BSTRIDE + n]);
                bh[j][1] = __float_as_uint(cBh[(kb + t4 + 4) * BSTRIDE + n]);
                bl[j][0] = __float_as_uint(cBl[(kb + t4) * BSTRIDE + n]);
                bl[j][1] = __float_as_uint(cBl[(kb + t4 + 4) * BSTRIDE + n]);
            }
            #pragma unroll
            for (int i = 0; i < 2; i++)
                #pragma unroll
                for (int j = 0; j < 4; j++) {
                    mma_tf32(acc[i][j], ah[i], bh[j]);
                    mma_tf32(acc[i][j], ah[i], bl[j]);
                    mma_tf32(acc[i][j], al[i], bh[j]);
                }
        }
        __syncthreads();
    }

    #pragma unroll
    for (int i = 0; i < 2; i++) {
        int r0 = row0 + wm + i * 16 + g;
        #pragma unroll
        for (int j = 0; j < 4; j++) {
            int c = col0 + wn + j * 8 + t4 * 2;
            if (r0 < N)
                *(float2*)(C + (size_t)r0 * HD + c) = make_float2(acc[i][j][0], acc[i][j][1]);
            if (r0 + 8 < N)
                *(float2*)(C + (size_t)(r0 + 8) * HD + c) = make_float2(acc[i][j][2], acc[i][j][3]);
        }
    }
}

// ---------------- attention-scalar dots ----------------
__global__ void avec_var_kernel(const float* __restrict__ xv, int l) {
    __shared__ float sv[6][HD];
    int t = threadIdx.x;
    sv[0][t] = g_WS[(4 * l + 0) * HD + t];
    sv[1][t] = g_WD[(4 * l + 0) * HD + t];
    sv[2][t] = g_WS[(4 * l + 1) * HD + t];
    sv[3][t] = g_WD[(4 * l + 1) * HD + t];
    sv[4][t] = g_WS[(4 * l + 2) * HD + t];
    sv[5][t] = g_WD[(4 * l + 3) * HD + t];
    __syncthreads();
    int w = (blockIdx.x * blockDim.x + t) >> 5;
    int lane = t & 31;
    if (w >= NVN) return;
    const float* row = xv + (size_t)w * HD;
    float s[6] = {0, 0, 0, 0, 0, 0};
    #pragma unroll
    for (int j0 = 0; j0 < HD; j0 += 32) {
        float x = row[j0 + lane];
        #pragma unroll
        for (int k = 0; k < 6; k++) s[k] += x * sv[k][j0 + lane];
    }
    #pragma unroll
    for (int k = 0; k < 6; k++)
        #pragma unroll
        for (int o = 16; o > 0; o >>= 1) s[k] += __shfl_xor_sync(0xffffffffu, s[k], o);
    if (lane == 0) {
        g_AS0[w] = s[0]; g_AD0[w] = s[1];
        g_AS1[w] = s[2]; g_AD1[w] = s[3];
        g_AS2[w] = s[4]; g_AD3[w] = s[5];
    }
}

__global__ void avec_con_kernel(const float* __restrict__ xc, int l) {
    __shared__ float sv[2][HD];
    int t = threadIdx.x;
    sv[0][t] = g_WD[(4 * l + 2) * HD + t];
    sv[1][t] = g_WS[(4 * l + 3) * HD + t];
    __syncthreads();
    int w = (blockIdx.x * blockDim.x + t) >> 5;
    int lane = t & 31;
    if (w >= NCN) return;
    const float* row = xc + (size_t)w * HD;
    float s0 = 0.f, s1 = 0.f;
    #pragma unroll
    for (int j0 = 0; j0 < HD; j0 += 32) {
        float x = row[j0 + lane];
        s0 += x * sv[0][j0 + lane];
        s1 += x * sv[1][j0 + lane];
    }
    #pragma unroll
    for (int o = 16; o > 0; o >>= 1) {
        s0 += __shfl_xor_sync(0xffffffffu, s0, o);
        s1 += __shfl_xor_sync(0xffffffffu, s1, o);
    }
    if (lane == 0) { g_AD2[w] = s0; g_AS3[w] = s1; }
}

// ---------------- CSR build ----------------
__global__ void zero_int_kernel(int* __restrict__ p, int n) {
    int i = blockIdx.x * blockDim.x + threadIdx.x;
    if (i < n) p[i] = 0;
}
__global__ void hist_kernel(const int* __restrict__ dst, int* __restrict__ cnt, int E) {
    int i = blockIdx.x * blockDim.x + threadIdx.x;
    if (i < E) atomicAdd(&cnt[dst[i]], 1);
}
// single-block exclusive scan (in-place over cnt -> rowptr), fills cursor too
__global__ void scan_kernel(int* __restrict__ rp, int* __restrict__ cursor, int n) {
    __shared__ int swarp[32];
    __shared__ int stot;
    int t = threadIdx.x, w = t >> 5, lane = t & 31;
    int carry = 0;
    for (int base = 0; base < n; base += 1024) {
        int idx = base + t;
        int v = (idx < n) ? rp[idx] : 0;
        int x = v;
        #pragma unroll
        for (int o = 1; o < 32; o <<= 1) {
            int y = __shfl_up_sync(0xffffffffu, x, o);
            if (lane >= o) x += y;
        }
        if (lane == 31) swarp[w] = x;
        __syncthreads();
        if (w == 0) {
            int s = swarp[lane];
            int z = s;
            #pragma unroll
            for (int o = 1; o < 32; o <<= 1) {
                int y = __shfl_up_sync(0xffffffffu, z, o);
                if (lane >= o) z += y;
            }
            swarp[lane] = z - s;       // exclusive warp offsets
            if (lane == 31) stot = z;  // chunk total
        }
        __syncthreads();
        int excl = carry + swarp[w] + (x - v);
        if (idx < n) { rp[idx] = excl; cursor[idx] = excl; }
        carry += stot;
        __syncthreads();
    }
    if (t == 0) rp[n] = carry;
}
__global__ void scatter_kernel(const int* __restrict__ src, const int* __restrict__ dst,
                               int* __restrict__ cursor, int* __restrict__ cs, int E) {
    int i = blockIdx.x * blockDim.x + threadIdx.x;
    if (i >= E) return;
    int pos = atomicAdd(&cursor[dst[i]], 1);
    cs[pos] = src[i];
}

// ---------------- fused GAT (warp per dst node) ----------------
__device__ __forceinline__ void gat_accum(
        int d, int lane,
        const int* __restrict__ rp, const int* __restrict__ cs,
        const float* __restrict__ AS, const float* __restrict__ AD,
        const float* __restrict__ XL,
        float4& acc0, float4& acc1) {
    int off = rp[d];
    int deg = rp[d + 1] - off;
    if (deg <= 0) return;
    float adv = AD[d];
    float m = -1e30f;
    for (int j = lane; j < deg; j += 32) {
        int s = cs[off + j];
        float e = AS[s] + adv;
        e = (e >= 0.f) ? e : 0.2f * e;
        m = fmaxf(m, e);
    }
    #pragma unroll
    for (int o = 16; o > 0; o >>= 1) m = fmaxf(m, __shfl_xor_sync(0xffffffffu, m, o));
    float den = 0.f;
    for (int j = lane; j < deg; j += 32) {
        int s = cs[off + j];
        float e = AS[s] + adv;
        e = (e >= 0.f) ? e : 0.2f * e;
        den += __expf(e - m);
    }
    #pragma unroll
    for (int o = 16; o > 0; o >>= 1) den += __shfl_xor_sync(0xffffffffu, den, o);
    float invden = 1.f / (den + 1e-16f);
    for (int c = 0; c < deg; c += 32) {
        int j = c + lane;
        int s = 0;
        float wgt = 0.f;
        if (j < deg) {
            s = cs[off + j];
            float e = AS[s] + adv;
            e = (e >= 0.f) ? e : 0.2f * e;
            wgt = __expf(e - m) * invden;
        }
        int cnt = min(32, deg - c);
        for (int jj = 0; jj < cnt; jj++) {
            float wj = __shfl_sync(0xffffffffu, wgt, jj);
            int   sj = __shfl_sync(0xffffffffu, s, jj);
            const float4* xs = (const float4*)(XL + (size_t)sj * HD);
            float4 v0 = xs[lane];
            float4 v1 = xs[32 + lane];
            acc0.x += wj * v0.x; acc0.y += wj * v0.y; acc0.z += wj * v0.z; acc0.w += wj * v0.w;
            acc1.x += wj * v1.x; acc1.y += wj * v1.y; acc1.z += wj * v1.z; acc1.w += wj * v1.w;
        }
    }
}

__global__ void gat_var_kernel(const float* __restrict__ XL0, const float* __restrict__ XL1,
                               const float* __restrict__ XL3,
                               const float* __restrict__ bias, int l,
                               float* __restrict__ out) {
    int w = (blockIdx.x * blockDim.x + threadIdx.x) >> 5;
    int lane = threadIdx.x & 31;
    if (w >= NVN) return;
    float4 acc0 = make_float4(0.f, 0.f, 0.f, 0.f);
    float4 acc1 = make_float4(0.f, 0.f, 0.f, 0.f);
    gat_accum(w, lane, g_RP0, g_CS0, g_AS0, g_AD0, XL0, acc0, acc1);
    gat_accum(w, lane, g_RP1, g_CS1, g_AS1, g_AD1, XL1, acc0, acc1);
    gat_accum(w, lane, g_RP3, g_CS3, g_AS3, g_AD3, XL3, acc0, acc1);
    const float4* b0 = (const float4*)(bias + (size_t)(4 * l + 0) * HD);
    const float4* b1 = (const float4*)(bias + (size_t)(4 * l + 1) * HD);
    const float4* b3 = (const float4*)(bias + (size_t)(4 * l + 3) * HD);
    float4 x0 = b0[lane], y0 = b1[lane], z0 = b3[lane];
    float4 x1 = b0[32 + lane], y1 = b1[32 + lane], z1 = b3[32 + lane];
    acc0.x += x0.x + y0.x + z0.x; acc0.y += x0.y + y0.y + z0.y;
    acc0.z += x0.z + y0.z + z0.z; acc0.w += x0.w + y0.w + z0.w;
    acc1.x += x1.x + y1.x + z1.x; acc1.y += x1.y + y1.y + z1.y;
    acc1.z += x1.z + y1.z + z1.z; acc1.w += x1.w + y1.w + z1.w;
    float4* ob = (float4*)(out + (size_t)w * HD);
    ob[lane] = acc0;
    ob[32 + lane] = acc1;
}

__global__ void gat_con_kernel(const float* __restrict__ XL2,
                               const float* __restrict__ bias, int l,
                               float* __restrict__ out) {
    int w = (blockIdx.x * blockDim.x + threadIdx.x) >> 5;
    int lane = threadIdx.x & 31;
    if (w >= NCN) return;
    float4 acc0 = make_float4(0.f, 0.f, 0.f, 0.f);
    float4 acc1 = make_float4(0.f, 0.f, 0.f, 0.f);
    gat_accum(w, lane, g_RP2, g_CS2, g_AS2, g_AD2, XL2, acc0, acc1);
    const float4* b2 = (const float4*)(bias + (size_t)(4 * l + 2) * HD);
    float4 x0 = b2[lane], x1 = b2[32 + lane];
    acc0.x += x0.x; acc0.y += x0.y; acc0.z += x0.z; acc0.w += x0.w;
    acc1.x += x1.x; acc1.y += x1.y; acc1.z += x1.z; acc1.w += x1.w;
    float4* ob = (float4*)(out + (size_t)w * HD);
    ob[lane] = acc0;
    ob[32 + lane] = acc1;
}

// ---------------- pooling + head ----------------
__global__ void zero_pool_kernel() {
    int i = blockIdx.x * 256 + threadIdx.x;
    g_VP[i] = 0.f;
    g_CP[i] = 0.f;
    if (i < 2 * GN) g_CNT[i] = 0;
}

__global__ void pool_kernel(const float* __restrict__ X, const int* __restrict__ batch,
                            int N, float* __restrict__ S, int* __restrict__ cnt) {
    int w = (blockIdx.x * blockDim.x + threadIdx.x) >> 5;
    int lane = threadIdx.x & 31;
    if (w >= N) return;
    int g = batch[w];
    if (lane == 0) atomicAdd(&cnt[g], 1);
    const float4* xr = (const float4*)(X + (size_t)w * HD);
    float* sb = S + (size_t)g * HD;
    #pragma unroll
    for (int j = 0; j < 2; j++) {
        int idx = lane + 32 * j;
        red4(sb + 4 * idx, xr[idx]);
    }
}

__global__ void finalize_kernel(const float* __restrict__ Wlin, const float* __restrict__ blin,
                                float* __restrict__ out) {
    int g = blockIdx.x, t = threadIdx.x;
    float cv = (float)max(g_CNT[g], 1);
    float cc = (float)max(g_CNT[GN + g], 1);
    float a = g_VP[g * HD + t] / cv;
    float c = g_CP[g * HD + t] / cc;
    float p0 = a * Wlin[t * 2 + 0] + c * Wlin[(HD + t) * 2 + 0];
    float p1 = a * Wlin[t * 2 + 1] + c * Wlin[(HD + t) * 2 + 1];
    __shared__ float s0[256], s1[256];
    s0[t] = p0; s1[t] = p1;
    __syncthreads();
    for (int o = 128; o > 0; o >>= 1) {
        if (t < o) { s0[t] += s0[t + o]; s1[t] += s1[t + o]; }
        __syncthreads();
    }
    if (t == 0) {
        float z0 = s0[0] + blin[0], z1 = s1[0] + blin[1];
        float m = fmaxf(z0, z1);
        float e0 = expf(z0 - m), e1 = expf(z1 - m);
        float inv = 1.f / (e0 + e1);
        out[2 * g + 0] = e0 * inv;
        out[2 * g + 1] = e1 * inv;
    }
}

// ---------------- host ----------------
extern "C" void kernel_launch(void* const* d_in, const int* in_sizes, int n_in,
                              void* d_out, int out_size) {
    const float* x_var   = (const float*)d_in[0];
    const float* x_con   = (const float*)d_in[1];
    const float* W_src   = (const float*)d_in[2];
    const float* W_dst   = (const float*)d_in[3];
    const float* att_src = (const float*)d_in[4];
    const float* att_dst = (const float*)d_in[5];
    const float* bias    = (const float*)d_in[6];
    const float* W_lin   = (const float*)d_in[7];
    const float* b_lin   = (const float*)d_in[8];
    const int* e_vv      = (const int*)d_in[9];
    const int* e_vv_rev  = (const int*)d_in[10];
    const int* e_vc      = (const int*)d_in[11];
    const int* e_cv      = (const int*)d_in[12];
    const int* batch_var = (const int*)d_in[13];
    const int* batch_con = (const int*)d_in[14];
    float* out = (float*)d_out;

    float *pXV[2], *pXC[2], *pXL0, *pXL1, *pXL2, *pXL3, *pVP, *pCP;
    float *pAhV, *pAlV, *pAhC, *pAlC, *pWh, *pWl;
    int *pRP0, *pRP1, *pRP2, *pRP3, *pCU0, *pCU1, *pCU2, *pCU3;
    int *pCS0, *pCS1, *pCS2, *pCS3, *pCNT;
    cudaGetSymbolAddress((void**)&pXV[0], g_XV0);
    cudaGetSymbolAddress((void**)&pXV[1], g_XV1);
    cudaGetSymbolAddress((void**)&pXC[0], g_XC0);
    cudaGetSymbolAddress((void**)&pXC[1], g_XC1);
    cudaGetSymbolAddress((void**)&pXL0, g_XL0);
    cudaGetSymbolAddress((void**)&pXL1, g_XL1);
    cudaGetSymbolAddress((void**)&pXL2, g_XL2);
    cudaGetSymbolAddress((void**)&pXL3, g_XL3);
    cudaGetSymbolAddress((void**)&pAhV, g_AhV);
    cudaGetSymbolAddress((void**)&pAlV, g_AlV);
    cudaGetSymbolAddress((void**)&pAhC, g_AhC);
    cudaGetSymbolAddress((void**)&pAlC, g_AlC);
    cudaGetSymbolAddress((void**)&pWh, g_Wh);
    cudaGetSymbolAddress((void**)&pWl, g_Wl);
    cudaGetSymbolAddress((void**)&pRP0, g_RP0);
    cudaGetSymbolAddress((void**)&pRP1, g_RP1);
    cudaGetSymbolAddress((void**)&pRP2, g_RP2);
    cudaGetSymbolAddress((void**)&pRP3, g_RP3);
    cudaGetSymbolAddress((void**)&pCU0, g_CU0);
    cudaGetSymbolAddress((void**)&pCU1, g_CU1);
    cudaGetSymbolAddress((void**)&pCU2, g_CU2);
    cudaGetSymbolAddress((void**)&pCU3, g_CU3);
    cudaGetSymbolAddress((void**)&pCS0, g_CS0);
    cudaGetSymbolAddress((void**)&pCS1, g_CS1);
    cudaGetSymbolAddress((void**)&pCS2, g_CS2);
    cudaGetSymbolAddress((void**)&pCS3, g_CS3);
    cudaGetSymbolAddress((void**)&pVP, g_VP);
    cudaGetSymbolAddress((void**)&pCP, g_CP);
    cudaGetSymbolAddress((void**)&pCNT, g_CNT);

    static bool attr_set = false;
    if (!attr_set) {
        cudaFuncSetAttribute(gemm_split_kernel,
                             cudaFuncAttributeMaxDynamicSharedMemorySize, SMEM_BYTES);
        attr_set = true;
    }

    const int EB = 256;

    // projection vectors + weight split (once per call)
    wsd_kernel<<<16, 256>>>(W_src, W_dst, att_src, att_dst);
    split_kernel<<<(16 * HD * HD / 4 + EB - 1) / EB, EB>>>(W_src, pWh, pWl, 16 * HD * HD / 4);

    // CSR build (once per call)
    zero_int_kernel<<<(NVN + 1 + EB - 1) / EB, EB>>>(pRP0, NVN + 1);
    zero_int_kernel<<<(NVN + 1 + EB - 1) / EB, EB>>>(pRP1, NVN + 1);
    zero_int_kernel<<<(NVN + 1 + EB - 1) / EB, EB>>>(pRP3, NVN + 1);
    zero_int_kernel<<<(NCN + 1 + EB - 1) / EB, EB>>>(pRP2, NCN + 1);
    hist_kernel<<<(EVVN + EB - 1) / EB, EB>>>(e_vv + EVVN, pRP0, EVVN);      // dst of vv
    hist_kernel<<<(EVVN + EB - 1) / EB, EB>>>(e_vv_rev + EVVN, pRP1, EVVN);  // dst of vv_rev
    hist_kernel<<<(EVCN + EB - 1) / EB, EB>>>(e_cv + EVCN, pRP3, EVCN);      // dst of cv (var)
    hist_kernel<<<(EVCN + EB - 1) / EB, EB>>>(e_vc + EVCN, pRP2, EVCN);      // dst of vc (con)
    scan_kernel<<<1, 1024>>>(pRP0, pCU0, NVN);
    scan_kernel<<<1, 1024>>>(pRP1, pCU1, NVN);
    scan_kernel<<<1, 1024>>>(pRP3, pCU3, NVN);
    scan_kernel<<<1, 1024>>>(pRP2, pCU2, NCN);
    scatter_kernel<<<(EVVN + EB - 1) / EB, EB>>>(e_vv, e_vv + EVVN, pCU0, pCS0, EVVN);
    scatter_kernel<<<(EVVN + EB - 1) / EB, EB>>>(e_vv_rev, e_vv_rev + EVVN, pCU1, pCS1, EVVN);
    scatter_kernel<<<(EVCN + EB - 1) / EB, EB>>>(e_cv, e_cv + EVCN, pCU3, pCS3, EVCN);
    scatter_kernel<<<(EVCN + EB - 1) / EB, EB>>>(e_vc, e_vc + EVCN, pCU2, pCS2, EVCN);

    dim3 gemmGridV((NVN + 127) / 128, 12);  // 3 mats x 4 col blocks
    dim3 gemmGridC((NCN + 127) / 128, 4);   // 1 mat

    for (int l = 0; l < NLAYER; l++) {
        const float* xv_in = (l == 0) ? x_var : pXV[(l + 1) & 1];
        const float* xc_in = (l == 0) ? x_con : pXC[(l + 1) & 1];
        float* xv_out = pXV[l & 1];
        float* xc_out = pXC[l & 1];

        split_kernel<<<(NVN * HD / 4 + EB - 1) / EB, EB>>>(xv_in, pAhV, pAlV, NVN * HD / 4);
        split_kernel<<<(NCN * HD / 4 + EB - 1) / EB, EB>>>(xc_in, pAhC, pAlC, NCN * HD / 4);

        gemm_split_kernel<<<gemmGridV, 256, SMEM_BYTES>>>(
            pAhV, pAlV, pWh + (size_t)(4 * l) * HD * HD, pWl + (size_t)(4 * l) * HD * HD,
            pXL0, pXL1, pXL2, NVN);
        gemm_split_kernel<<<gemmGridC, 256, SMEM_BYTES>>>(
            pAhC, pAlC, pWh + (size_t)(4 * l + 3) * HD * HD, pWl + (size_t)(4 * l + 3) * HD * HD,
            pXL3, pXL3, pXL3, NCN);

        avec_var_kernel<<<(NVN * 32 + EB - 1) / EB, EB>>>(xv_in, l);
        avec_con_kernel<<<(NCN * 32 + EB - 1) / EB, EB>>>(xc_in, l);

        gat_var_kernel<<<(NVN * 32 + EB - 1) / EB, EB>>>(pXL0, pXL1, pXL3, bias, l, xv_out);
        gat_con_kernel<<<(NCN * 32 + EB - 1) / EB, EB>>>(pXL2, bias, l, xc_out);
    }

    zero_pool_kernel<<<GN, 256>>>();
    pool_kernel<<<(NVN * 32 + EB - 1) / EB, EB>>>(pXV[(NLAYER - 1) & 1], batch_var, NVN, pVP, pCNT);
    pool_kernel<<<(NCN * 32 + EB - 1) / EB, EB>>>(pXC[(NLAYER - 1) & 1], batch_con, NCN, pCP, pCNT + GN);
    finalize_kernel<<<GN, 256>>>(W_lin, b_lin, out);
}